// round 4
// baseline (speedup 1.0000x reference)
#include <cuda_runtime.h>
#include <cuda_bf16.h>
#include <math.h>

// loss_soft_add, single fused kernel, R4:
// 128-row tiles with BOTH pre and tar staged in smem (25.6KB total);
// each thread processes half a row (3 chunks of 4) -> no o[24] register
// array, regs<=32, 8 blocks/SM resident (occ ~100%).
// Cross-block finish: threadfence + self-resetting atomicInc (graph-safe).

#define THREADS        256
#define ROWS_PER_TILE  128
#define ROW_LEN        25
#define FLOATS_PER_TILE (ROWS_PER_TILE * ROW_LEN)   // 3200
#define VEC4_PER_TILE   (FLOATS_PER_TILE / 4)       // 800
#define MAX_GRID 1184

__device__ double g_partials[MAX_GRID];
__device__ unsigned int g_count = 0;   // wraps back to 0 every launch

// 3 chunks (12 elems) of fused 3*softmax + L1 diff
__device__ __forceinline__ float half_row_loss(const float* __restrict__ p,
                                               const float* __restrict__ t)
{
    float s = 0.0f;
    #pragma unroll
    for (int j = 0; j < 3; j++) {
        float a = p[4 * j + 0];
        float b = p[4 * j + 1];
        float c = p[4 * j + 2];
        float d = p[4 * j + 3];
        float m = fmaxf(fmaxf(a, b), fmaxf(c, d));
        float ea = __expf(a - m);
        float eb = __expf(b - m);
        float ec = __expf(c - m);
        float ed = __expf(d - m);
        float inv = 3.0f / (ea + eb + ec + ed);
        s += fabsf(ea * inv - t[4 * j + 0]);
        s += fabsf(eb * inv - t[4 * j + 1]);
        s += fabsf(ec * inv - t[4 * j + 2]);
        s += fabsf(ed * inv - t[4 * j + 3]);
    }
    return s;
}

__global__ __launch_bounds__(THREADS, 8)
void loss_kernel(const float* __restrict__ pre,
                 const float* __restrict__ tar,
                 long long nrows,
                 float* __restrict__ out)
{
    __shared__ float spre[FLOATS_PER_TILE];
    __shared__ float star[FLOATS_PER_TILE];
    __shared__ float warp_red[8];
    __shared__ bool isLast;

    const int tid  = threadIdx.x;
    const int lane = tid & 31;
    const int wid  = tid >> 5;
    const int row  = tid & (ROWS_PER_TILE - 1);  // 0..127
    const int half = tid >> 7;                   // 0 or 1 (per-warp constant)
    const int off  = row * ROW_LEN + half * 12;  // conflict-free per warp

    const long long ntiles = nrows / ROWS_PER_TILE;

    float acc = 0.0f;

    for (long long tile = blockIdx.x; tile < ntiles; tile += gridDim.x) {
        const long long base = tile * (long long)FLOATS_PER_TILE;

        // ---- stage PRE + TAR tiles (coalesced float4, high MLP) ----
        {
            const float4* p4 = reinterpret_cast<const float4*>(pre + base);
            const float4* t4 = reinterpret_cast<const float4*>(tar + base);
            float4* sp = reinterpret_cast<float4*>(spre);
            float4* st = reinterpret_cast<float4*>(star);
            #pragma unroll
            for (int i = tid; i < VEC4_PER_TILE; i += THREADS) {
                sp[i] = p4[i];
                st[i] = t4[i];
            }
        }
        __syncthreads();

        // ---- fused 3*softmax + L1 diff on this thread's half-row ----
        acc += half_row_loss(spre + off, star + off);
        __syncthreads();   // before next tile overwrites smem
    }

    // ---- tail rows (nrows % 128): block 0, threads 0..rem-1, full rows ----
    {
        const long long done = ntiles * (long long)ROWS_PER_TILE;
        const long long rem = nrows - done;
        if (blockIdx.x == 0 && (long long)tid < rem) {
            const float* prow = pre + (done + tid) * (long long)ROW_LEN;
            const float* trow = tar + (done + tid) * (long long)ROW_LEN;
            acc += half_row_loss(prow, trow);
            acc += half_row_loss(prow + 12, trow + 12);
        }
    }

    // ---- block reduction: warp shuffle + 8-entry smem ----
    #pragma unroll
    for (int o = 16; o > 0; o >>= 1)
        acc += __shfl_down_sync(0xFFFFFFFFu, acc, o);
    if (lane == 0) warp_red[wid] = acc;
    __syncthreads();
    if (wid == 0) {
        float v = (lane < 8) ? warp_red[lane] : 0.0f;
        #pragma unroll
        for (int o = 4; o > 0; o >>= 1)
            v += __shfl_down_sync(0xFFFFFFFFu, v, o);

        if (lane == 0) {
            g_partials[blockIdx.x] = (double)v;
            __threadfence();
            unsigned int old = atomicInc(&g_count, gridDim.x - 1);
            isLast = (old == gridDim.x - 1);
        }
    }
    __syncthreads();

    // ---- last block reduces all partials (deterministic) ----
    if (isLast) {
        __threadfence();
        double s = 0.0;
        for (int i = tid; i < (int)gridDim.x; i += THREADS)
            s += g_partials[i];
        #pragma unroll
        for (int o = 16; o > 0; o >>= 1)
            s += __shfl_down_sync(0xFFFFFFFFu, s, o);
        __shared__ double dred[8];
        if (lane == 0) dred[wid] = s;
        __syncthreads();
        if (wid == 0) {
            double v = (lane < 8) ? dred[lane] : 0.0;
            #pragma unroll
            for (int o = 4; o > 0; o >>= 1)
                v += __shfl_down_sync(0xFFFFFFFFu, v, o);
            if (lane == 0)
                out[0] = (float)(v * (1.0 / 24.0));
        }
    }
}

extern "C" void kernel_launch(void* const* d_in, const int* in_sizes, int n_in,
                              void* d_out, int out_size)
{
    const float* pre = (const float*)d_in[0];
    const float* tar = (const float*)d_in[1];
    long long nrows = (long long)in_sizes[0] / ROW_LEN;
    long long ntiles = nrows / ROWS_PER_TILE;

    long long g = ntiles > 0 ? ntiles : 1;
    int grid = (int)(g < MAX_GRID ? g : MAX_GRID);

    loss_kernel<<<grid, THREADS>>>(pre, tar, nrows, (float*)d_out);
}

// round 5
// speedup vs baseline: 1.3980x; 1.3980x over previous
#include <cuda_runtime.h>
#include <cuda_bf16.h>
#include <math.h>
#include <stdint.h>

// loss_soft_add R5: TMA (cp.async.bulk) double-buffered pipeline.
// Per row of 25 floats: 6 chunks of 4 -> 3*softmax, L1 diff vs tar over
// first 24 cols, mean/24, summed over all rows -> single float scalar.
//
// One elected thread bulk-copies tile k+1 (pre+tar, 2x12.8KB) into the
// alternate smem stage while 256 threads compute tile k. mbarrier
// full/empty pairs give backpressure. Cross-block finish: threadfence +
// self-resetting atomicInc (graph-replay safe, deterministic).

#define THREADS      256
#define ROWS         128
#define ROW_LEN      25
#define TILE_FLOATS  (ROWS * ROW_LEN)     // 3200
#define TILE_BYTES   (TILE_FLOATS * 4)    // 12800
#define STAGE_FLOATS (2 * TILE_FLOATS)    // pre + tar = 6400 floats
#define SMEM_BYTES   (2 * STAGE_FLOATS * 4)  // 2 stages = 51200 B
#define MAX_GRID     1184

__device__ double g_partials[MAX_GRID];
__device__ unsigned int g_count = 0;   // wraps back to 0 every launch

__device__ __forceinline__ uint32_t smem_u32(const void* p) {
    uint32_t a;
    asm("{ .reg .u64 t; cvta.to.shared.u64 t, %1; cvt.u32.u64 %0, t; }"
        : "=r"(a) : "l"(p));
    return a;
}

__device__ __forceinline__ void mbar_init(uint32_t a, uint32_t cnt) {
    asm volatile("mbarrier.init.shared.b64 [%0], %1;" :: "r"(a), "r"(cnt) : "memory");
}
__device__ __forceinline__ void mbar_expect_tx(uint32_t a, uint32_t bytes) {
    asm volatile("mbarrier.arrive.expect_tx.shared.b64 _, [%0], %1;"
                 :: "r"(a), "r"(bytes) : "memory");
}
__device__ __forceinline__ void mbar_arrive(uint32_t a) {
    asm volatile("mbarrier.arrive.shared.b64 _, [%0];" :: "r"(a) : "memory");
}
__device__ __forceinline__ void mbar_wait(uint32_t a, uint32_t parity) {
    uint32_t done;
    asm volatile(
        "{\n\t.reg .pred p;\n\t"
        "mbarrier.try_wait.parity.acquire.cta.shared::cta.b64 p, [%1], %2;\n\t"
        "selp.b32 %0, 1, 0, p;\n\t}"
        : "=r"(done) : "r"(a), "r"(parity) : "memory");
    if (!done) {
        asm volatile(
            "{\n\t.reg .pred P1;\n\t"
            "WL_%=:\n\t"
            "mbarrier.try_wait.parity.acquire.cta.shared::cta.b64 P1, [%0], %1, 0x989680;\n\t"
            "@P1 bra.uni WD_%=;\n\t"
            "bra.uni WL_%=;\n\t"
            "WD_%=:\n\t}"
            :: "r"(a), "r"(parity) : "memory");
    }
}
__device__ __forceinline__ void bulk_g2s(uint32_t dst, const void* src,
                                         uint32_t bytes, uint32_t mbar) {
    asm volatile(
        "cp.async.bulk.shared::cluster.global.mbarrier::complete_tx::bytes "
        "[%0], [%1], %2, [%3];"
        :: "r"(dst), "l"(src), "r"(bytes), "r"(mbar) : "memory");
}

// 3 chunks (12 elems) of fused 3*softmax + L1 diff
__device__ __forceinline__ float half_row_loss(const float* __restrict__ p,
                                               const float* __restrict__ t)
{
    float s = 0.0f;
    #pragma unroll
    for (int j = 0; j < 3; j++) {
        float a = p[4 * j + 0];
        float b = p[4 * j + 1];
        float c = p[4 * j + 2];
        float d = p[4 * j + 3];
        float m = fmaxf(fmaxf(a, b), fmaxf(c, d));
        float ea = __expf(a - m);
        float eb = __expf(b - m);
        float ec = __expf(c - m);
        float ed = __expf(d - m);
        float inv = 3.0f / (ea + eb + ec + ed);
        s += fabsf(ea * inv - t[4 * j + 0]);
        s += fabsf(eb * inv - t[4 * j + 1]);
        s += fabsf(ec * inv - t[4 * j + 2]);
        s += fabsf(ed * inv - t[4 * j + 3]);
    }
    return s;
}

__global__ __launch_bounds__(THREADS)
void loss_kernel(const float* __restrict__ pre,
                 const float* __restrict__ tar,
                 long long nrows,
                 float* __restrict__ out)
{
    extern __shared__ float smem[];   // [2][STAGE_FLOATS]: {pre,tar} x 2 stages
    __shared__ __align__(8) uint64_t bars[4];   // full0, full1, empty0, empty1
    __shared__ float warp_red[8];
    __shared__ bool isLast;

    const int tid  = threadIdx.x;
    const int lane = tid & 31;
    const int wid  = tid >> 5;
    const int row  = tid & (ROWS - 1);
    const int half = tid >> 7;                   // 0/1, per-warp constant
    const int off  = row * ROW_LEN + half * 12;  // stride-25: conflict-free

    const uint32_t bar0   = smem_u32(bars);
    const uint32_t smem0  = smem_u32(smem);
    const long long ntiles = nrows / ROWS;

    if (tid == 0) {
        mbar_init(bar0 + 0, 1);        // full0 (expect_tx arrive)
        mbar_init(bar0 + 8, 1);        // full1
        mbar_init(bar0 + 16, THREADS); // empty0
        mbar_init(bar0 + 24, THREADS); // empty1
    }
    asm volatile("fence.proxy.async.shared::cta;" ::: "memory");
    __syncthreads();

    float acc = 0.0f;

    // ---- prologue: fill stage 0 with this block's first tile ----
    if (tid == 0 && blockIdx.x < ntiles) {
        const long long base = (long long)blockIdx.x * TILE_FLOATS;
        mbar_expect_tx(bar0 + 0, 2 * TILE_BYTES);
        bulk_g2s(smem0,                pre + base, TILE_BYTES, bar0 + 0);
        bulk_g2s(smem0 + TILE_BYTES,   tar + base, TILE_BYTES, bar0 + 0);
    }

    long long k = 0;
    for (long long tile = blockIdx.x; tile < ntiles; tile += gridDim.x, k++) {
        const int s = (int)(k & 1);

        // ---- producer: pre-issue tile k+1 into the other stage ----
        if (tid == 0) {
            const long long nt = tile + gridDim.x;
            if (nt < ntiles) {
                const int t = s ^ 1;
                const long long f = (k + 1) >> 1;            // fill index of stage t
                if (f >= 1)
                    mbar_wait(bar0 + 16 + 8 * t, (uint32_t)((f - 1) & 1));
                const long long base = nt * (long long)TILE_FLOATS;
                const uint32_t dst = smem0 + (uint32_t)t * (2 * TILE_BYTES);
                mbar_expect_tx(bar0 + 8 * t, 2 * TILE_BYTES);
                bulk_g2s(dst,              pre + base, TILE_BYTES, bar0 + 8 * t);
                bulk_g2s(dst + TILE_BYTES, tar + base, TILE_BYTES, bar0 + 8 * t);
            }
        }

        // ---- consumer: wait for current stage, compute, release ----
        mbar_wait(bar0 + 8 * s, (uint32_t)((k >> 1) & 1));
        const float* p = smem + s * STAGE_FLOATS;
        acc += half_row_loss(p + off, p + TILE_FLOATS + off);
        mbar_arrive(bar0 + 16 + 8 * s);
    }

    // ---- tail rows (nrows % 128): block 0, direct from GMEM ----
    {
        const long long done = ntiles * (long long)ROWS;
        const long long rem = nrows - done;
        if (blockIdx.x == 0 && (long long)tid < rem) {
            const float* prow = pre + (done + tid) * (long long)ROW_LEN;
            const float* trow = tar + (done + tid) * (long long)ROW_LEN;
            acc += half_row_loss(prow, trow);
            acc += half_row_loss(prow + 12, trow + 12);
        }
    }

    // ---- block reduction: warp shuffle + 8-entry smem ----
    #pragma unroll
    for (int o = 16; o > 0; o >>= 1)
        acc += __shfl_down_sync(0xFFFFFFFFu, acc, o);
    if (lane == 0) warp_red[wid] = acc;
    __syncthreads();
    if (wid == 0) {
        float v = (lane < 8) ? warp_red[lane] : 0.0f;
        #pragma unroll
        for (int o = 4; o > 0; o >>= 1)
            v += __shfl_down_sync(0xFFFFFFFFu, v, o);

        if (lane == 0) {
            g_partials[blockIdx.x] = (double)v;
            __threadfence();
            unsigned int old = atomicInc(&g_count, gridDim.x - 1);
            isLast = (old == gridDim.x - 1);
        }
    }
    __syncthreads();

    // ---- last block reduces all partials (deterministic) ----
    if (isLast) {
        __threadfence();
        double sum = 0.0;
        for (int i = tid; i < (int)gridDim.x; i += THREADS)
            sum += g_partials[i];
        #pragma unroll
        for (int o = 16; o > 0; o >>= 1)
            sum += __shfl_down_sync(0xFFFFFFFFu, sum, o);
        __shared__ double dred[8];
        if (lane == 0) dred[wid] = sum;
        __syncthreads();
        if (wid == 0) {
            double v = (lane < 8) ? dred[lane] : 0.0;
            #pragma unroll
            for (int o = 4; o > 0; o >>= 1)
                v += __shfl_down_sync(0xFFFFFFFFu, v, o);
            if (lane == 0)
                out[0] = (float)(v * (1.0 / 24.0));
        }
    }
}

extern "C" void kernel_launch(void* const* d_in, const int* in_sizes, int n_in,
                              void* d_out, int out_size)
{
    const float* pre = (const float*)d_in[0];
    const float* tar = (const float*)d_in[1];
    long long nrows = (long long)in_sizes[0] / ROW_LEN;
    long long ntiles = nrows / ROWS;

    static bool attr_set = false;
    if (!attr_set) {
        cudaFuncSetAttribute(loss_kernel,
                             cudaFuncAttributeMaxDynamicSharedMemorySize,
                             SMEM_BYTES);
        attr_set = true;
    }

    // 148 SMs x 4 resident blocks (51.2KB dyn smem each)
    long long g = ntiles > 0 ? ntiles : 1;
    int grid = (int)(g < 592 ? g : 592);

    loss_kernel<<<grid, THREADS, SMEM_BYTES>>>(pre, tar, nrows, (float*)d_out);
}